// round 14
// baseline (speedup 1.0000x reference)
#include <cuda_runtime.h>
#include <cuda_fp16.h>
#include <cstdint>

// ============================================================================
// L2LOptimizer via warp-level HMMA (mma.sync.m16n8k16).
//   W_all[256,128] fp16 = [W_ih@W2 | W_hh]; K = [relu1(64) | h0(64)]
//   WARP = GATE-COL SLICE: warp w owns cols w*8..w*8+7 of each gate (its own
//   8 KB B slice, L1::evict_last resident) and iterates over ALL 8 m16 tiles
//   of the CTA -> B traffic per element drops 8x vs per-warp-all-B.
//   Per-row cross-warp partial sums of h1*W_out reduced through smem.
//   CTA: 256 thr / 8 warps / 128 elements, 3 CTAs/SM (occ 37.5%).
// ============================================================================

#define TPB 256

// padded row stride: 272 B (17 x 16B) -> conflict-free ldmatrix
#define ASTRIDE 272
#define SM_A    0
#define SM_BEFF (SM_A + 128 * ASTRIDE)      // 34816
#define SM_WOUT (SM_BEFF + 256 * 4)         // 35840
#define SM_PART (SM_WOUT + 64 * 4)          // 36096: [8 warps][128 rows] f32
#define SM_BYTES (SM_PART + 8 * 128 * 4)    // 40192

__device__ float g_beff[256];
// B fragments (uint2 = {k0..k0+1, k0+8..k0+9} half2s for n8 x k16 tile):
// index ((p*8+kt)*4+g)*32 + lane ; gate-cols g*64 + p*8..+7, K-slice kt*16..+15
__device__ uint2 g_Bfrag2[8192];

// ---------------- helpers ---------------------------------------------------
__device__ __forceinline__ uint32_t smem_u32(const void* p) {
    uint32_t a;
    asm("{ .reg .u64 t; cvta.to.shared.u64 t, %1; cvt.u32.u64 %0, t; }"
        : "=r"(a) : "l"(p));
    return a;
}
__device__ __forceinline__ void ldsm_x4(uint32_t& r0, uint32_t& r1,
                                        uint32_t& r2, uint32_t& r3,
                                        uint32_t addr) {
    asm volatile("ldmatrix.sync.aligned.m8n8.x4.shared.b16 {%0,%1,%2,%3}, [%4];"
                 : "=r"(r0), "=r"(r1), "=r"(r2), "=r"(r3) : "r"(addr));
}
__device__ __forceinline__ void mma16816(float* c,
                                         uint32_t a0, uint32_t a1,
                                         uint32_t a2, uint32_t a3,
                                         uint32_t b0, uint32_t b1) {
    asm volatile(
        "mma.sync.aligned.m16n8k16.row.col.f32.f16.f16.f32 "
        "{%0,%1,%2,%3}, {%4,%5,%6,%7}, {%8,%9}, {%0,%1,%2,%3};"
        : "+f"(c[0]), "+f"(c[1]), "+f"(c[2]), "+f"(c[3])
        : "r"(a0), "r"(a1), "r"(a2), "r"(a3), "r"(b0), "r"(b1));
}
// B load: keep resident in L1 (evict_last)
__device__ __forceinline__ uint2 ldg_b_keep(const uint2* p) {
    uint2 v;
    asm volatile("ld.global.nc.L1::evict_last.v2.u32 {%0,%1}, [%2];"
                 : "=r"(v.x), "=r"(v.y) : "l"(p));
    return v;
}
__device__ __forceinline__ float tanha(float x) {
    float y;
    asm("tanh.approx.f32 %0, %1;" : "=f"(y) : "f"(x));
    return y;
}
__device__ __forceinline__ float sigm(float x) {
    return fmaf(0.5f, tanha(0.5f * x), 0.5f);
}

// ---- prep: one half2 per thread (16384 threads, 64 blocks) -----------------
__global__ void __launch_bounds__(256)
l2l_prep(const float* __restrict__ W_ih, const float* __restrict__ W2,
         const float* __restrict__ b2,   const float* __restrict__ b_ih,
         const float* __restrict__ b_hh, const float* __restrict__ W_hh)
{
    __shared__ float sW2[4096];          // W2 [t][k] row-major (64x64)
    const int tid = threadIdx.x;
    for (int i = tid; i < 4096; i += 256) sW2[i] = W2[i];
    __syncthreads();

    const int u    = blockIdx.x * 256 + tid;   // 0..16383
    const int c    = u & 1;                    // uint2 component (x/y)
    const int lane = (u >> 1) & 31;
    const int t    = u >> 6;                   // (p*8+kt)*4+g
    const int g    = t & 3;
    const int kt   = (t >> 2) & 7;
    const int p    = t >> 5;                   // 0..7

    const int n  = g * 64 + p * 8 + (lane >> 2);
    const int k0 = kt * 16 + (lane & 3) * 2 + c * 8;

    float v0, v1;
    if (kt < 4) {                              // W_ih @ W2 block
        v0 = 0.f; v1 = 0.f;
        const float* wr = W_ih + n * 64;
        #pragma unroll
        for (int q = 0; q < 64; q++) {
            const float w = __ldg(wr + q);
            v0 = fmaf(w, sW2[q * 64 + k0],     v0);
            v1 = fmaf(w, sW2[q * 64 + k0 + 1], v1);
        }
    } else {                                   // W_hh block
        const float* wr = W_hh + n * 64 + (k0 - 64);
        v0 = __ldg(wr); v1 = __ldg(wr + 1);
    }
    __half2 h = __floats2half2_rn(v0, v1);
    ((uint32_t*)g_Bfrag2)[u] = *(uint32_t*)&h;

    if (u < 256) {
        float b = b_ih[u] + b_hh[u];
        const float* wr = W_ih + u * 64;
        #pragma unroll
        for (int q = 0; q < 64; q++)
            b = fmaf(__ldg(wr + q), b2[q], b);
        g_beff[u] = b;
    }
}

// ---- main kernel -----------------------------------------------------------
__global__ void __launch_bounds__(TPB, 3)
l2l_main(const float* __restrict__ grad, const float* __restrict__ par,
         const float* __restrict__ mom,  const float* __restrict__ h0,
         const float* __restrict__ c0,
         const float* __restrict__ W1,   const float* __restrict__ b1,
         const float* __restrict__ W_out, const float* __restrict__ b_out,
         float* __restrict__ out)
{
    extern __shared__ char smem[];
    const uint32_t sb = smem_u32(smem);
    const int tid  = threadIdx.x;
    const int lane = tid & 31;
    const int warp = tid >> 5;           // 0..7 = gate-col slice (p)
    const int grpd = lane >> 2;          // 0..7
    const int tig  = lane & 3;           // 0..3
    const int e0   = blockIdx.x * 128;

    // ---- stage biases
    ((float*)(smem + SM_BEFF))[tid] = g_beff[tid];
    if (tid < 64)
        ((float*)(smem + SM_WOUT))[tid] = W_out[tid];

    // ---- stage A: relu1 (k 0..63); 2 threads per element (16 pairs each)
    {
        const int e_l  = tid >> 1;              // 0..127
        const int e    = e0 + e_l;
        const int pk0  = (tid & 1) * 16;
        const float g = __ldcs(grad + e);
        const float p = __ldcs(par + e);
        const float m = fmaf(0.9f, __ldcs(mom + e), g);
        #pragma unroll
        for (int q = 0; q < 16; q++) {
            const int pk = pk0 + q;
            float v0 = b1[2 * pk], v1 = b1[2 * pk + 1];
            v0 = fmaf(W1[(2 * pk) * 3 + 0], g, v0);
            v0 = fmaf(W1[(2 * pk) * 3 + 1], p, v0);
            v0 = fmaf(W1[(2 * pk) * 3 + 2], m, v0);
            v1 = fmaf(W1[(2 * pk + 1) * 3 + 0], g, v1);
            v1 = fmaf(W1[(2 * pk + 1) * 3 + 1], p, v1);
            v1 = fmaf(W1[(2 * pk + 1) * 3 + 2], m, v1);
            __half2 h = __floats2half2_rn(fmaxf(v0, 0.f), fmaxf(v1, 0.f));
            *(uint32_t*)(smem + SM_A + e_l * ASTRIDE + pk * 4) = *(uint32_t*)&h;
        }
    }
    // ---- stage A: h0 (k 64..127), cooperative coalesced, evict-first
    #pragma unroll 4
    for (int idx = tid; idx < 128 * 32; idx += TPB) {
        int row = idx >> 5;
        int pk  = idx & 31;
        float2 v = __ldcs((const float2*)(h0 + (size_t)(e0 + row) * 64 + pk * 2));
        __half2 h = __floats2half2_rn(v.x, v.y);
        *(uint32_t*)(smem + SM_A + row * ASTRIDE + 128 + pk * 4) =
            *(uint32_t*)&h;
    }
    __syncthreads();

    const float* sbeff = (const float*)(smem + SM_BEFF);
    const float* swout = (const float*)(smem + SM_WOUT);
    float*       spart = (float*)(smem + SM_PART) + warp * 128;

    // per-lane ldmatrix address pattern (row-within-tile from lane)
    const uint32_t aBase = sb + SM_A + (lane & 15) * ASTRIDE +
                           ((lane >> 4) & 1) * 16;
    const uint2* bf = g_Bfrag2 + (size_t)warp * 1024 + lane;

    // ---- iterate over all 8 m16 tiles of the CTA (this warp's col-slice)
    #pragma unroll 1
    for (int mt = 0; mt < 8; mt++) {
        // prefetch c0 for this tile's epilogue (cols warp*8 + tig*2)
        float2 cv[2];
        #pragma unroll
        for (int hh = 0; hh < 2; hh++) {
            const int row = 16 * mt + 8 * hh + grpd;
            cv[hh] = __ldcs((const float2*)(c0 + (size_t)(e0 + row) * 64 +
                                            warp * 8 + tig * 2));
        }

        // A fragments for this tile (all 8 kt)
        uint32_t afr[8][4];
        const uint32_t aAddr = aBase + 16 * mt * ASTRIDE;
        #pragma unroll
        for (int kt = 0; kt < 8; kt++)
            ldsm_x4(afr[kt][0], afr[kt][1], afr[kt][2], afr[kt][3],
                    aAddr + kt * 32);

        float acc[4][4];                 // [gate][frag]
        #pragma unroll
        for (int g = 0; g < 4; g++)
            #pragma unroll
            for (int q = 0; q < 4; q++)
                acc[g][q] = 0.f;

        #pragma unroll
        for (int kt = 0; kt < 8; kt++) {
            #pragma unroll
            for (int g = 0; g < 4; g++) {
                const uint2 b = ldg_b_keep(bf + (kt * 4 + g) * 32);
                mma16816(acc[g], afr[kt][0], afr[kt][1],
                         afr[kt][2], afr[kt][3], b.x, b.y);
            }
        }

        // ---- epilogue: LSTM pointwise for cols warp*8..+7, rows of tile mt
        #pragma unroll
        for (int hh = 0; hh < 2; hh++) {
            float us = 0.f;
            #pragma unroll
            for (int ee = 0; ee < 2; ee++) {
                const int j = warp * 8 + tig * 2 + ee;
                const int q = hh * 2 + ee;
                const float ai = acc[0][q] + sbeff[j];
                const float af = acc[1][q] + sbeff[j + 64];
                const float ag = acc[2][q] + sbeff[j + 128];
                const float ao = acc[3][q] + sbeff[j + 192];
                const float is = sigm(ai), fs = sigm(af), os = sigm(ao);
                const float gt = tanha(ag);
                const float c0v = (ee == 0) ? cv[hh].x : cv[hh].y;
                const float c1 = fmaf(fs, c0v, is * gt);
                const float h1 = os * tanha(c1);
                us = fmaf(h1, swout[j], us);
            }
            // reduce the 4 tig lanes -> one partial per row
            us += __shfl_xor_sync(0xffffffffu, us, 1);
            us += __shfl_xor_sync(0xffffffffu, us, 2);
            if (tig == 0)
                spart[16 * mt + 8 * hh + grpd] = us;
        }
    }
    __syncthreads();

    // ---- final cross-warp reduction: 128 threads, one row each
    if (tid < 128) {
        const float* pp = (const float*)(smem + SM_PART) + tid;
        float v = b_out[0];
        #pragma unroll
        for (int w = 0; w < 8; w++)
            v += pp[w * 128];
        __stcs(out + e0 + tid, v);
    }
}

// ---- launch ----------------------------------------------------------------
extern "C" void kernel_launch(void* const* d_in, const int* in_sizes, int n_in,
                              void* d_out, int out_size)
{
    const float* grad  = (const float*)d_in[0];
    const float* par   = (const float*)d_in[1];
    const float* mom   = (const float*)d_in[2];
    const float* h0    = (const float*)d_in[3];
    const float* c0    = (const float*)d_in[4];
    const float* W1    = (const float*)d_in[5];
    const float* b1    = (const float*)d_in[6];
    const float* W2    = (const float*)d_in[7];
    const float* b2    = (const float*)d_in[8];
    const float* W_ih  = (const float*)d_in[9];
    const float* W_hh  = (const float*)d_in[10];
    const float* b_ih  = (const float*)d_in[11];
    const float* b_hh  = (const float*)d_in[12];
    const float* W_out = (const float*)d_in[13];
    const float* b_out = (const float*)d_in[14];
    float* out = (float*)d_out;

    const int B = in_sizes[0];

    cudaFuncSetAttribute(l2l_main, cudaFuncAttributeMaxDynamicSharedMemorySize,
                         SM_BYTES);

    l2l_prep<<<64, 256>>>(W_ih, W2, b2, b_ih, b_hh, W_hh);

    const int nblk = B / 128;
    l2l_main<<<nblk, TPB, SM_BYTES>>>(grad, par, mom, h0, c0,
                                      W1, b1, W_out, b_out, out);
}

// round 15
// speedup vs baseline: 1.4405x; 1.4405x over previous
#include <cuda_runtime.h>
#include <cuda_fp16.h>
#include <cstdint>

// ============================================================================
// L2LOptimizer via warp-level HMMA (mma.sync.m16n8k16).
//   W_all[256,128] fp16 = [W_ih@W2 | W_hh]; K = [relu1(64) | h0(64)]
//   m64 PER WARP: warp w owns rows 64w..64w+63 (4 m16 tiles) and loops all 8
//   col-passes -> each B fragment LDG.64 feeds 16 mmas (4 m-tiles) =>
//   B traffic 1 KB/elem (vs 4 KB at m16). A streamed per (kt) via ldsm
//   (transient 16 regs) so regs stay ~115 (no spills, cap 170).
//   CTA: 128 thr / 4 warps / 256 elements; 3 CTAs/SM (smem 71 KB).
//   No cross-warp reduction: warp computes full gates for its own rows.
// ============================================================================

#define TPB 128

// padded row stride: 272 B (17 x 16B) -> conflict-free ldmatrix
#define ASTRIDE 272
#define SM_A    0
#define SM_BEFF (SM_A + 256 * ASTRIDE)      // 69632
#define SM_WOUT (SM_BEFF + 256 * 4)         // 70656
#define SM_BYTES (SM_WOUT + 64 * 4)         // 70912

__device__ float g_beff[256];
// B fragments (uint2 = {k0..k0+1, k0+8..k0+9} half2s for n8 x k16 tile):
// index ((p*8+kt)*4+g)*32 + lane ; gate-cols g*64 + p*8..+7, K-slice kt*16..+15
__device__ uint2 g_Bfrag2[8192];

// ---------------- helpers ---------------------------------------------------
__device__ __forceinline__ uint32_t smem_u32(const void* p) {
    uint32_t a;
    asm("{ .reg .u64 t; cvta.to.shared.u64 t, %1; cvt.u32.u64 %0, t; }"
        : "=r"(a) : "l"(p));
    return a;
}
__device__ __forceinline__ void ldsm_x4(uint32_t& r0, uint32_t& r1,
                                        uint32_t& r2, uint32_t& r3,
                                        uint32_t addr) {
    asm volatile("ldmatrix.sync.aligned.m8n8.x4.shared.b16 {%0,%1,%2,%3}, [%4];"
                 : "=r"(r0), "=r"(r1), "=r"(r2), "=r"(r3) : "r"(addr));
}
__device__ __forceinline__ void mma16816(float* c,
                                         uint32_t a0, uint32_t a1,
                                         uint32_t a2, uint32_t a3,
                                         uint32_t b0, uint32_t b1) {
    asm volatile(
        "mma.sync.aligned.m16n8k16.row.col.f32.f16.f16.f32 "
        "{%0,%1,%2,%3}, {%4,%5,%6,%7}, {%8,%9}, {%0,%1,%2,%3};"
        : "+f"(c[0]), "+f"(c[1]), "+f"(c[2]), "+f"(c[3])
        : "r"(a0), "r"(a1), "r"(a2), "r"(a3), "r"(b0), "r"(b1));
}
// B load: keep resident in L1 (evict_last)
__device__ __forceinline__ uint2 ldg_b_keep(const uint2* p) {
    uint2 v;
    asm volatile("ld.global.nc.L1::evict_last.v2.u32 {%0,%1}, [%2];"
                 : "=r"(v.x), "=r"(v.y) : "l"(p));
    return v;
}
__device__ __forceinline__ float tanha(float x) {
    float y;
    asm("tanh.approx.f32 %0, %1;" : "=f"(y) : "f"(x));
    return y;
}
__device__ __forceinline__ float sigm(float x) {
    return fmaf(0.5f, tanha(0.5f * x), 0.5f);
}

// ---- prep: one half2 per thread (16384 threads, 64 blocks) -----------------
__global__ void __launch_bounds__(256)
l2l_prep(const float* __restrict__ W_ih, const float* __restrict__ W2,
         const float* __restrict__ b2,   const float* __restrict__ b_ih,
         const float* __restrict__ b_hh, const float* __restrict__ W_hh)
{
    __shared__ float sW2[4096];          // W2 [t][k] row-major (64x64)
    const int tid = threadIdx.x;
    for (int i = tid; i < 4096; i += 256) sW2[i] = W2[i];
    __syncthreads();

    const int u    = blockIdx.x * 256 + tid;   // 0..16383
    const int c    = u & 1;                    // uint2 component (x/y)
    const int lane = (u >> 1) & 31;
    const int t    = u >> 6;                   // (p*8+kt)*4+g
    const int g    = t & 3;
    const int kt   = (t >> 2) & 7;
    const int p    = t >> 5;                   // 0..7

    const int n  = g * 64 + p * 8 + (lane >> 2);
    const int k0 = kt * 16 + (lane & 3) * 2 + c * 8;

    float v0, v1;
    if (kt < 4) {                              // W_ih @ W2 block
        v0 = 0.f; v1 = 0.f;
        const float* wr = W_ih + n * 64;
        #pragma unroll
        for (int q = 0; q < 64; q++) {
            const float w = __ldg(wr + q);
            v0 = fmaf(w, sW2[q * 64 + k0],     v0);
            v1 = fmaf(w, sW2[q * 64 + k0 + 1], v1);
        }
    } else {                                   // W_hh block
        const float* wr = W_hh + n * 64 + (k0 - 64);
        v0 = __ldg(wr); v1 = __ldg(wr + 1);
    }
    __half2 h = __floats2half2_rn(v0, v1);
    ((uint32_t*)g_Bfrag2)[u] = *(uint32_t*)&h;

    if (u < 256) {
        float b = b_ih[u] + b_hh[u];
        const float* wr = W_ih + u * 64;
        #pragma unroll
        for (int q = 0; q < 64; q++)
            b = fmaf(__ldg(wr + q), b2[q], b);
        g_beff[u] = b;
    }
}

// ---- main kernel -----------------------------------------------------------
__global__ void __launch_bounds__(TPB, 3)
l2l_main(const float* __restrict__ grad, const float* __restrict__ par,
         const float* __restrict__ mom,  const float* __restrict__ h0,
         const float* __restrict__ c0,
         const float* __restrict__ W1,   const float* __restrict__ b1,
         const float* __restrict__ W_out, const float* __restrict__ b_out,
         float* __restrict__ out)
{
    extern __shared__ char smem[];
    const uint32_t sb = smem_u32(smem);
    const int tid  = threadIdx.x;
    const int lane = tid & 31;
    const int warp = tid >> 5;           // 0..3 -> rows 64w..64w+63
    const int grpd = lane >> 2;          // 0..7
    const int tig  = lane & 3;           // 0..3
    const int e0   = blockIdx.x * 256;

    // ---- stage biases
    ((float*)(smem + SM_BEFF))[tid]       = g_beff[tid];
    ((float*)(smem + SM_BEFF))[tid + 128] = g_beff[tid + 128];
    if (tid < 64)
        ((float*)(smem + SM_WOUT))[tid] = W_out[tid];

    // ---- stage A: relu1 (k 0..63); each thread does 2 elements
    #pragma unroll
    for (int r = 0; r < 2; r++) {
        const int e_l = tid + r * 128;          // 0..255
        const int e   = e0 + e_l;
        const float g = __ldcs(grad + e);
        const float p = __ldcs(par + e);
        const float m = fmaf(0.9f, __ldcs(mom + e), g);
        #pragma unroll
        for (int pk = 0; pk < 32; pk++) {
            float v0 = b1[2 * pk], v1 = b1[2 * pk + 1];
            v0 = fmaf(W1[(2 * pk) * 3 + 0], g, v0);
            v0 = fmaf(W1[(2 * pk) * 3 + 1], p, v0);
            v0 = fmaf(W1[(2 * pk) * 3 + 2], m, v0);
            v1 = fmaf(W1[(2 * pk + 1) * 3 + 0], g, v1);
            v1 = fmaf(W1[(2 * pk + 1) * 3 + 1], p, v1);
            v1 = fmaf(W1[(2 * pk + 1) * 3 + 2], m, v1);
            __half2 h = __floats2half2_rn(fmaxf(v0, 0.f), fmaxf(v1, 0.f));
            *(uint32_t*)(smem + SM_A + e_l * ASTRIDE + pk * 4) = *(uint32_t*)&h;
        }
    }
    // ---- stage A: h0 (k 64..127), float4 -> STS.64, cooperative coalesced
    #pragma unroll 4
    for (int idx = tid; idx < 256 * 16; idx += TPB) {
        int row = idx >> 4;
        int q4  = idx & 15;                    // float4 index within row
        float4 v = __ldcs((const float4*)(h0 + (size_t)(e0 + row) * 64 + q4 * 4));
        __half2 hA = __floats2half2_rn(v.x, v.y);
        __half2 hB = __floats2half2_rn(v.z, v.w);
        uint2 pk2 = make_uint2(*(uint32_t*)&hA, *(uint32_t*)&hB);
        *(uint2*)(smem + SM_A + row * ASTRIDE + 128 + q4 * 8) = pk2;
    }
    __syncthreads();

    const float* sbeff = (const float*)(smem + SM_BEFF);
    const float* swout = (const float*)(smem + SM_WOUT);
    const float  bo    = b_out[0];

    // ldmatrix base: rows 64*warp + 16*mt + (lane&15), halves by lane>>4
    const uint32_t aBase = sb + SM_A + (64 * warp + (lane & 15)) * ASTRIDE +
                           ((lane >> 4) & 1) * 16;

    float updr[4][2];                    // [mtile][row half]
    #pragma unroll
    for (int mt = 0; mt < 4; mt++) { updr[mt][0] = 0.f; updr[mt][1] = 0.f; }

    #pragma unroll 1
    for (int p = 0; p < 8; p++) {        // 8 gate-cols per pass
        float acc[4][4][4];              // [mt][gate][frag] = 64 regs
        #pragma unroll
        for (int mt = 0; mt < 4; mt++)
            #pragma unroll
            for (int g = 0; g < 4; g++)
                #pragma unroll
                for (int q = 0; q < 4; q++)
                    acc[mt][g][q] = 0.f;

        const uint2* bf = g_Bfrag2 + (size_t)p * 1024 + lane;

        #pragma unroll
        for (int kt = 0; kt < 8; kt++) {
            uint32_t a[4][4];            // A fragments for 4 m-tiles at kt
            #pragma unroll
            for (int mt = 0; mt < 4; mt++)
                ldsm_x4(a[mt][0], a[mt][1], a[mt][2], a[mt][3],
                        aBase + 16 * mt * ASTRIDE + kt * 32);
            uint2 b[4];
            #pragma unroll
            for (int g = 0; g < 4; g++)
                b[g] = ldg_b_keep(bf + (kt * 4 + g) * 32);
            #pragma unroll
            for (int g = 0; g < 4; g++)
                #pragma unroll
                for (int mt = 0; mt < 4; mt++)
                    mma16816(acc[mt][g], a[mt][0], a[mt][1], a[mt][2], a[mt][3],
                             b[g].x, b[g].y);
        }

        // ---- epilogue: LSTM pointwise (cols p*8..p*8+7), rows of this warp
        #pragma unroll
        for (int mt = 0; mt < 4; mt++) {
            #pragma unroll
            for (int hh = 0; hh < 2; hh++) {
                const int row = 64 * warp + 16 * mt + 8 * hh + grpd;
                const float2 cv = __ldcs((const float2*)(c0 +
                                     (size_t)(e0 + row) * 64 + p * 8 + tig * 2));
                float us = 0.f;
                #pragma unroll
                for (int ee = 0; ee < 2; ee++) {
                    const int j = p * 8 + tig * 2 + ee;
                    const int q = hh * 2 + ee;
                    const float ai = acc[mt][0][q] + sbeff[j];
                    const float af = acc[mt][1][q] + sbeff[j + 64];
                    const float ag = acc[mt][2][q] + sbeff[j + 128];
                    const float ao = acc[mt][3][q] + sbeff[j + 192];
                    const float is = sigm(ai), fs = sigm(af), os = sigm(ao);
                    const float gt = tanha(ag);
                    const float c0v = (ee == 0) ? cv.x : cv.y;
                    const float c1 = fmaf(fs, c0v, is * gt);
                    const float h1 = os * tanha(c1);
                    us = fmaf(h1, swout[j], us);
                }
                updr[mt][hh] += us;
            }
        }
    }

    // ---- reduce over the 4 tig lanes of each row group, write out
    #pragma unroll
    for (int mt = 0; mt < 4; mt++) {
        #pragma unroll
        for (int hh = 0; hh < 2; hh++) {
            float v = updr[mt][hh];
            v += __shfl_xor_sync(0xffffffffu, v, 1);
            v += __shfl_xor_sync(0xffffffffu, v, 2);
            if (tig == 0) {
                const int row = 64 * warp + 16 * mt + 8 * hh + grpd;
                __stcs(out + e0 + row, v + bo);
            }
        }
    }
}

// ---- launch ----------------------------------------------------------------
extern "C" void kernel_launch(void* const* d_in, const int* in_sizes, int n_in,
                              void* d_out, int out_size)
{
    const float* grad  = (const float*)d_in[0];
    const float* par   = (const float*)d_in[1];
    const float* mom   = (const float*)d_in[2];
    const float* h0    = (const float*)d_in[3];
    const float* c0    = (const float*)d_in[4];
    const float* W1    = (const float*)d_in[5];
    const float* b1    = (const float*)d_in[6];
    const float* W2    = (const float*)d_in[7];
    const float* b2    = (const float*)d_in[8];
    const float* W_ih  = (const float*)d_in[9];
    const float* W_hh  = (const float*)d_in[10];
    const float* b_ih  = (const float*)d_in[11];
    const float* b_hh  = (const float*)d_in[12];
    const float* W_out = (const float*)d_in[13];
    const float* b_out = (const float*)d_in[14];
    float* out = (float*)d_out;

    const int B = in_sizes[0];

    cudaFuncSetAttribute(l2l_main, cudaFuncAttributeMaxDynamicSharedMemorySize,
                         SM_BYTES);

    l2l_prep<<<64, 256>>>(W_ih, W2, b2, b_ih, b_hh, W_hh);

    const int nblk = B / 256;
    l2l_main<<<nblk, TPB, SM_BYTES>>>(grad, par, mom, h0, c0,
                                      W1, b1, W_out, b_out, out);
}